// round 11
// baseline (speedup 1.0000x reference)
#include <cuda_runtime.h>

// Decoder: T_IN=12, B=65536, H=64, T_OUT=12, OVERLAP=3
// 128 threads / 16 batches per CTA.
//   Phase A (attention+out): 8-lane group owns one batch, lane owns 8 dims,
//                            plain float4 fp32 math (R8 form — ALU-lean).
//            Writes hA (fp32) AND a pre-converted tf32 A-fragment buffer.
//   Phase B: tf32 mma.sync.m16n8k8; A-frags via conflict-free LDS.64 from
//            the tf32 buffer; B-frags (W_hh) packed as uint4 kt-pairs.
// MMA inputs and accumulation order bit-identical to R8/R9.

#define FULLMASK 0xFFFFFFFFu

constexpr int T_IN  = 12;
constexpr int T_OUT = 12;
constexpr int Bz    = 65536;
constexpr int WARPS = 4;
constexpr int THREADS = WARPS * 32;
constexpr int BPC   = 16;            // batches per CTA
constexpr int HPAD  = 68;            // fp32 h row pitch (floats)
constexpr int APITCH = 36;           // tf32 A-buffer pitch in uint2 (72 words)

// SMEM float offsets
constexpr int WFR_N    = 4 * 6 * 4 * 32;              // warps x nt x ktp x lane (uint4)
constexpr int OFF_ATF  = WFR_N * 4;                   // 12288
constexpr int OFF_HA   = OFF_ATF + BPC * APITCH * 2;  // +1152
constexpr int OFF_HG   = OFF_HA + BPC * HPAD;         // +1088
constexpr int OFF_L    = OFF_HG + BPC * HPAD;         // +1088
constexpr int OFF_GP   = OFF_L + BPC * 4;
constexpr int OFF_BH   = OFF_GP + 192 * 4;
constexpr int OFF_WL   = OFF_BH + 192;
constexpr int SMEM_FLOATS = OFF_WL + 64;
constexpr int SMEM_BYTES  = SMEM_FLOATS * 4;          // ~66.8 KB -> 2 CTAs/SM

__device__ __forceinline__ unsigned cvt_tf32(float x) {
    unsigned r;
    asm("cvt.rna.tf32.f32 %0, %1;" : "=r"(r) : "f"(x));
    return r;
}
__device__ __forceinline__ void mma_tf32(float& d0, float& d1, float& d2, float& d3,
                                         unsigned a0, unsigned a1, unsigned a2, unsigned a3,
                                         unsigned b0, unsigned b1) {
    asm("mma.sync.aligned.m16n8k8.row.col.f32.tf32.tf32.f32 "
        "{%0,%1,%2,%3}, {%4,%5,%6,%7}, {%8,%9}, {%0,%1,%2,%3};"
        : "+f"(d0), "+f"(d1), "+f"(d2), "+f"(d3)
        : "r"(a0), "r"(a1), "r"(a2), "r"(a3), "r"(b0), "r"(b1));
}
__device__ __forceinline__ float sigf(float x) {
    return __fdividef(1.0f, 1.0f + __expf(-x));
}
__device__ __forceinline__ float tanhfast(float x) {
    return __fdividef(2.0f, 1.0f + __expf(-2.0f * x)) - 1.0f;
}
__device__ __forceinline__ float dot8(float4 a, float4 b, float4 c, float4 d) {
    float s = a.x * b.x;
    s = fmaf(a.y, b.y, s); s = fmaf(a.z, b.z, s); s = fmaf(a.w, b.w, s);
    s = fmaf(c.x, d.x, s); s = fmaf(c.y, d.y, s);
    s = fmaf(c.z, d.z, s); s = fmaf(c.w, d.w, s);
    return s;
}

__global__ void __launch_bounds__(THREADS, 2)
decoder_kernel(const float* __restrict__ enc,    // (12, B, 64)
               const float* __restrict__ hid0,   // (B, 64)
               const float* __restrict__ last,   // (B, 3)
               const float* __restrict__ Wih,    // (192, 3)
               const float* __restrict__ Whh,    // (192, 64)
               const float* __restrict__ bih,    // (192)
               const float* __restrict__ bhh,    // (192)
               const float* __restrict__ Wlin,   // (1, 64)
               const float* __restrict__ blin,   // (1)
               float* __restrict__ out)          // (B, 12)
{
    extern __shared__ float smem[];
    uint4*  Wfr  = reinterpret_cast<uint4*>(smem);
    uint2*  atf  = reinterpret_cast<uint2*>(smem + OFF_ATF);
    float*  hAsh = smem + OFF_HA;
    float*  hGsh = smem + OFF_HG;
    float4* Lsh  = reinterpret_cast<float4*>(smem + OFF_L);
    float4* gpsh = reinterpret_cast<float4*>(smem + OFF_GP);   // {wih0,1,2,bih}
    float*  bhsh = smem + OFF_BH;
    float*  wlsh = smem + OFF_WL;

    const int tid  = threadIdx.x;
    const int lane = tid & 31;
    const int w    = tid >> 5;
    const int cb0  = blockIdx.x * BPC;

    // ---- stage W_hh into uint4 kt-pair B-fragment layout (tf32), once ----
    // Wfr[((ww*6+nt)*4+ktp)*32+ln] = {b0(kt0),b1(kt0),b0(kt1),b1(kt1)}
    // kt0 = 2*ktp, kt1 = 2*ktp+1; j = (nt>>1)*64 + ww*16 + (nt&1)*8 + (ln>>2)
    for (int i = tid; i < WFR_N; i += THREADS) {
        int ww  = i / 768;
        int rem = i - ww * 768;
        int nt  = rem >> 7;
        int rm2 = rem & 127;
        int ktp = rm2 >> 5;
        int ln  = rm2 & 31;
        int gg  = ln >> 2, t4 = ln & 3;
        int j   = ((nt >> 1) << 6) + ww * 16 + ((nt & 1) << 3) + gg;
        int k0  = ktp * 16;  // kt0*8
        Wfr[i] = make_uint4(cvt_tf32(__ldg(&Whh[j * 64 + k0 + t4])),
                            cvt_tf32(__ldg(&Whh[j * 64 + k0 + t4 + 4])),
                            cvt_tf32(__ldg(&Whh[j * 64 + k0 + 8 + t4])),
                            cvt_tf32(__ldg(&Whh[j * 64 + k0 + 8 + t4 + 4])));
    }
    // ---- stage params ----
    for (int j = tid; j < 192; j += THREADS) {
        gpsh[j] = make_float4(__ldg(&Wih[j * 3 + 0]), __ldg(&Wih[j * 3 + 1]),
                              __ldg(&Wih[j * 3 + 2]), __ldg(&bih[j]));
        bhsh[j] = __ldg(&bhh[j]);
    }
    if (tid < 64) wlsh[tid] = __ldg(&Wlin[tid]);
    // ---- stage hG = hid0 (padded rows), Lsh = last ----
    {
        const float4* hid04 = reinterpret_cast<const float4*>(hid0);
        for (int i = tid; i < BPC * 16; i += THREADS) {
            int b = i >> 4, c = i & 15;
            *reinterpret_cast<float4*>(hGsh + b * HPAD + c * 4) =
                __ldg(&hid04[(cb0 + b) * 16 + c]);
        }
    }
    if (tid < BPC) {
        int gb = cb0 + tid;
        Lsh[tid] = make_float4(__ldg(&last[gb * 3 + 0]),
                               __ldg(&last[gb * 3 + 1]),
                               __ldg(&last[gb * 3 + 2]), 0.0f);
    }

    // ---- Phase A identity: 8-lane group -> one batch, lane -> 8 dims
    const int sub = lane >> 3, lg = lane & 7;
    const int bA  = w * 4 + sub;
    const int gbA = cb0 + bA;
    const float4* Wl4 = reinterpret_cast<const float4*>(Wlin);
    const float4 wl0 = __ldg(&Wl4[lg * 2]);
    const float4 wl1 = __ldg(&Wl4[lg * 2 + 1]);
    const float  bl  = __ldg(blin);

    // encoder slice in registers: 12 t x 8 dims
    const float4* enc4 = reinterpret_cast<const float4*>(enc);
    float4 ev0[T_IN], ev1[T_IN];
#pragma unroll
    for (int t = 0; t < T_IN; t++) {
        int idx = (t * Bz + gbA) * 16 + lg * 2;
        ev0[t] = __ldg(&enc4[idx]);
        ev1[t] = __ldg(&enc4[idx + 1]);
    }

    // ---- Phase B identity: MMA fragment coords
    const int g  = lane >> 2;     // groupID 0..7
    const int t4 = lane & 3;      // threadID-in-group

    __syncthreads();

#pragma unroll 1
    for (int step = 0; step < T_OUT; step++) {
        // ================= Phase A: out(step-1) + attention =================
        float4 h0 = *reinterpret_cast<const float4*>(hGsh + bA * HPAD + lg * 8);
        float4 h1 = *reinterpret_cast<const float4*>(hGsh + bA * HPAD + lg * 8 + 4);

        if (step > 0) {
            float o = dot8(h0, wl0, h1, wl1);
            o += __shfl_xor_sync(FULLMASK, o, 4);
            o += __shfl_xor_sync(FULLMASK, o, 2);
            o += __shfl_xor_sync(FULLMASK, o, 1);
            o += bl;
            if (lg == 0) {
                float4 L = Lsh[bA];
                out[gbA * T_OUT + step - 1] = o;
                Lsh[bA] = make_float4(o, L.x, L.y, 0.0f);
            }
        }

        float p[T_IN];
#pragma unroll
        for (int t = 0; t < T_IN; t++)
            p[t] = dot8(ev0[t], h0, ev1[t], h1);
#pragma unroll
        for (int off = 4; off > 0; off >>= 1)
#pragma unroll
            for (int t = 0; t < T_IN; t++)
                p[t] += __shfl_xor_sync(FULLMASK, p[t], off);

        float m = p[0];
#pragma unroll
        for (int t = 1; t < T_IN; t++) m = fmaxf(m, p[t]);
        float s = 0.0f;
#pragma unroll
        for (int t = 0; t < T_IN; t++) { p[t] = __expf(p[t] - m); s += p[t]; }
        float inv = __fdividef(1.0f, s);

        float4 c0 = make_float4(0.f, 0.f, 0.f, 0.f);
        float4 c1 = make_float4(0.f, 0.f, 0.f, 0.f);
#pragma unroll
        for (int t = 0; t < T_IN; t++) {
            c0.x = fmaf(p[t], ev0[t].x, c0.x); c0.y = fmaf(p[t], ev0[t].y, c0.y);
            c0.z = fmaf(p[t], ev0[t].z, c0.z); c0.w = fmaf(p[t], ev0[t].w, c0.w);
            c1.x = fmaf(p[t], ev1[t].x, c1.x); c1.y = fmaf(p[t], ev1[t].y, c1.y);
            c1.z = fmaf(p[t], ev1[t].z, c1.z); c1.w = fmaf(p[t], ev1[t].w, c1.w);
        }
        h0.x = fmaf(c0.x, inv, h0.x); h0.y = fmaf(c0.y, inv, h0.y);
        h0.z = fmaf(c0.z, inv, h0.z); h0.w = fmaf(c0.w, inv, h0.w);
        h1.x = fmaf(c1.x, inv, h1.x); h1.y = fmaf(c1.y, inv, h1.y);
        h1.z = fmaf(c1.z, inv, h1.z); h1.w = fmaf(c1.w, inv, h1.w);

        // fp32 hA (for hprev in gates)
        *reinterpret_cast<float4*>(hAsh + bA * HPAD + lg * 8)     = h0;
        *reinterpret_cast<float4*>(hAsh + bA * HPAD + lg * 8 + 4) = h1;
        // tf32 A-fragment copy: atf[bat*APITCH + lg*4 + t4] =
        //   {tf32(h[lg*8+t4]), tf32(h[lg*8+t4+4])}
        {
            uint4* dst = reinterpret_cast<uint4*>(atf + bA * APITCH + lg * 4);
            dst[0] = make_uint4(cvt_tf32(h0.x), cvt_tf32(h1.x),
                                cvt_tf32(h0.y), cvt_tf32(h1.y));
            dst[1] = make_uint4(cvt_tf32(h0.z), cvt_tf32(h1.z),
                                cvt_tf32(h0.w), cvt_tf32(h1.w));
        }
        __syncthreads();

        // ============ Phase B: gh = hA @ W_hh^T via tf32 MMA ============
        float acc[6][4];
#pragma unroll
        for (int nt = 0; nt < 6; nt++)
#pragma unroll
            for (int ci = 0; ci < 4; ci++) acc[nt][ci] = 0.0f;

#pragma unroll
        for (int ktp = 0; ktp < 4; ktp++) {
            int kt0 = 2 * ktp;
            // A frags: uint2 {a0,a2} for batch row g; {a1,a3} for row g+8
            uint2 A0g0 = atf[g * APITCH + kt0 * 4 + t4];
            uint2 A0g8 = atf[(g + 8) * APITCH + kt0 * 4 + t4];
            uint2 A1g0 = atf[g * APITCH + kt0 * 4 + 4 + t4];
            uint2 A1g8 = atf[(g + 8) * APITCH + kt0 * 4 + 4 + t4];
#pragma unroll
            for (int nt = 0; nt < 6; nt++) {
                uint4 bv = Wfr[(((w * 6) + nt) * 4 + ktp) * 32 + lane];
                mma_tf32(acc[nt][0], acc[nt][1], acc[nt][2], acc[nt][3],
                         A0g0.x, A0g8.x, A0g0.y, A0g8.y, bv.x, bv.y);
                mma_tf32(acc[nt][0], acc[nt][1], acc[nt][2], acc[nt][3],
                         A1g0.x, A1g8.x, A1g0.y, A1g8.y, bv.z, bv.w);
            }
        }

        // ---- gates: lane covers batches {g, g+8} x dims {w16+ntp8+2t4, +1}
        float4 Lg0 = Lsh[g];
        float4 Lg8 = Lsh[g + 8];
#pragma unroll
        for (int ntp = 0; ntp < 2; ntp++) {
#pragma unroll
            for (int d01 = 0; d01 < 2; d01++) {
                int dim = w * 16 + ntp * 8 + 2 * t4 + d01;
                float4 gpr = gpsh[dim];
                float4 gpz = gpsh[64 + dim];
                float4 gpn = gpsh[128 + dim];
                float bhr = bhsh[dim], bhz = bhsh[64 + dim], bhn = bhsh[128 + dim];
#pragma unroll
                for (int bb = 0; bb < 2; bb++) {
                    int bat = g + 8 * bb;
                    float4 L = bb ? Lg8 : Lg0;
                    int ci = bb * 2 + d01;
                    float ghr = acc[ntp][ci]     + bhr;
                    float ghz = acc[ntp + 2][ci] + bhz;
                    float ghn = acc[ntp + 4][ci] + bhn;
                    float gir = fmaf(gpr.x, L.x, fmaf(gpr.y, L.y, fmaf(gpr.z, L.z, gpr.w)));
                    float giz = fmaf(gpz.x, L.x, fmaf(gpz.y, L.y, fmaf(gpz.z, L.z, gpz.w)));
                    float gin = fmaf(gpn.x, L.x, fmaf(gpn.y, L.y, fmaf(gpn.z, L.z, gpn.w)));
                    float r = sigf(gir + ghr);
                    float z = sigf(giz + ghz);
                    float n = tanhfast(fmaf(r, ghn, gin));
                    float hprev = hAsh[bat * HPAD + dim];
                    hGsh[bat * HPAD + dim] = fmaf(z, hprev - n, n);
                }
            }
        }
        __syncthreads();
    }

    // ---- final output (step T_OUT-1) from hG ----
    {
        float4 h0 = *reinterpret_cast<const float4*>(hGsh + bA * HPAD + lg * 8);
        float4 h1 = *reinterpret_cast<const float4*>(hGsh + bA * HPAD + lg * 8 + 4);
        float o = dot8(h0, wl0, h1, wl1);
        o += __shfl_xor_sync(FULLMASK, o, 4);
        o += __shfl_xor_sync(FULLMASK, o, 2);
        o += __shfl_xor_sync(FULLMASK, o, 1);
        o += bl;
        if (lg == 0) out[gbA * T_OUT + T_OUT - 1] = o;
    }
}

extern "C" void kernel_launch(void* const* d_in, const int* in_sizes, int n_in,
                              void* d_out, int out_size) {
    const float* enc  = (const float*)d_in[0];
    const float* hid0 = (const float*)d_in[1];
    const float* last = (const float*)d_in[2];
    const float* Wih  = (const float*)d_in[3];
    const float* Whh  = (const float*)d_in[4];
    const float* bih  = (const float*)d_in[5];
    const float* bhh  = (const float*)d_in[6];
    const float* Wlin = (const float*)d_in[7];
    const float* blin = (const float*)d_in[8];
    float* out = (float*)d_out;

    cudaFuncSetAttribute(decoder_kernel,
                         cudaFuncAttributeMaxDynamicSharedMemorySize,
                         SMEM_BYTES);

    dim3 grid(Bz / BPC);   // 4096 CTAs
    decoder_kernel<<<grid, THREADS, SMEM_BYTES>>>(
        enc, hid0, last, Wih, Whh, bih, bhh, Wlin, blin, out);
}

// round 12
// speedup vs baseline: 1.0765x; 1.0765x over previous
#include <cuda_runtime.h>

// Decoder: T_IN=12, B=65536, H=64, T_OUT=12, OVERLAP=3
// 128 threads / 16 batches per CTA.  (R8 structure + latency shaping)
//   Phase A (attention+out): 8-lane group owns one batch, lane owns 8 dims,
//                            plain float4 fp32 math.
//   Phase B (GRU matvec): tf32 mma.sync.m16n8k8 — M=16 batches, each warp
//                         computes 48 rows (dims w*16..+15 for gates r,z,n).
//   W_hh staged once into SMEM pre-swizzled in B-fragment layout (tf32).
//   kt=0 B-fragments prefetched BEFORE the barrier (step-invariant data).

#define FULLMASK 0xFFFFFFFFu

constexpr int T_IN  = 12;
constexpr int T_OUT = 12;
constexpr int Bz    = 65536;
constexpr int WARPS = 4;
constexpr int THREADS = WARPS * 32;
constexpr int BPC   = 16;            // batches per CTA
constexpr int HPAD  = 68;            // padded row pitch (floats) for hA/hG

// SMEM float offsets
constexpr int WFRAG_N   = 4 * 6 * 8 * 32;      // warps x ntile x ktile x lane (uint2)
constexpr int OFF_HA    = WFRAG_N * 2;          // 12288
constexpr int OFF_HG    = OFF_HA + BPC * HPAD;  // +1088
constexpr int OFF_L     = OFF_HG + BPC * HPAD;  // +1088
constexpr int OFF_GP    = OFF_L + BPC * 4;      // +64
constexpr int OFF_BH    = OFF_GP + 192 * 4;     // +768
constexpr int OFF_WL    = OFF_BH + 192;         // +192
constexpr int SMEM_FLOATS = OFF_WL + 64;
constexpr int SMEM_BYTES  = SMEM_FLOATS * 4;    // 62,208 B

__device__ __forceinline__ unsigned cvt_tf32(float x) {
    unsigned r;
    asm("cvt.rna.tf32.f32 %0, %1;" : "=r"(r) : "f"(x));
    return r;
}
__device__ __forceinline__ void mma_tf32(float& d0, float& d1, float& d2, float& d3,
                                         unsigned a0, unsigned a1, unsigned a2, unsigned a3,
                                         unsigned b0, unsigned b1) {
    asm("mma.sync.aligned.m16n8k8.row.col.f32.tf32.tf32.f32 "
        "{%0,%1,%2,%3}, {%4,%5,%6,%7}, {%8,%9}, {%0,%1,%2,%3};"
        : "+f"(d0), "+f"(d1), "+f"(d2), "+f"(d3)
        : "r"(a0), "r"(a1), "r"(a2), "r"(a3), "r"(b0), "r"(b1));
}
__device__ __forceinline__ float sigf(float x) {
    return __fdividef(1.0f, 1.0f + __expf(-x));
}
__device__ __forceinline__ float tanhfast(float x) {
    return __fdividef(2.0f, 1.0f + __expf(-2.0f * x)) - 1.0f;
}
__device__ __forceinline__ float dot8(float4 a, float4 b, float4 c, float4 d) {
    float s = a.x * b.x;
    s = fmaf(a.y, b.y, s); s = fmaf(a.z, b.z, s); s = fmaf(a.w, b.w, s);
    s = fmaf(c.x, d.x, s); s = fmaf(c.y, d.y, s);
    s = fmaf(c.z, d.z, s); s = fmaf(c.w, d.w, s);
    return s;
}

__global__ void __launch_bounds__(THREADS, 2)
decoder_kernel(const float* __restrict__ enc,    // (12, B, 64)
               const float* __restrict__ hid0,   // (B, 64)
               const float* __restrict__ last,   // (B, 3)
               const float* __restrict__ Wih,    // (192, 3)
               const float* __restrict__ Whh,    // (192, 64)
               const float* __restrict__ bih,    // (192)
               const float* __restrict__ bhh,    // (192)
               const float* __restrict__ Wlin,   // (1, 64)
               const float* __restrict__ blin,   // (1)
               float* __restrict__ out)          // (B, 12)
{
    extern __shared__ float smem[];
    uint2*  Wfr  = reinterpret_cast<uint2*>(smem);
    float*  hAsh = smem + OFF_HA;
    float*  hGsh = smem + OFF_HG;
    float4* Lsh  = reinterpret_cast<float4*>(smem + OFF_L);
    float4* gpsh = reinterpret_cast<float4*>(smem + OFF_GP);   // {wih0,1,2,bih}
    float*  bhsh = smem + OFF_BH;
    float*  wlsh = smem + OFF_WL;

    const int tid  = threadIdx.x;
    const int lane = tid & 31;
    const int w    = tid >> 5;
    const int cb0  = blockIdx.x * BPC;

    // ---- stage W_hh into B-fragment layout (tf32), once ----
    // Wfr[((ww*6+nt)*8+kt)*32 + ln] = {W[j][kt*8+t4], W[j][kt*8+t4+4]} (tf32)
    // where j = (nt>>1)*64 + ww*16 + (nt&1)*8 + (ln>>2), t4 = ln&3
    for (int i = tid; i < WFRAG_N; i += THREADS) {
        int ww  = i / 1536;
        int rem = i - ww * 1536;
        int nt  = rem >> 8;
        int rm2 = rem & 255;
        int kt  = rm2 >> 5;
        int ln  = rm2 & 31;
        int gg  = ln >> 2, t4 = ln & 3;
        int j   = ((nt >> 1) << 6) + ww * 16 + ((nt & 1) << 3) + gg;
        float b0 = __ldg(&Whh[j * 64 + kt * 8 + t4]);
        float b1 = __ldg(&Whh[j * 64 + kt * 8 + t4 + 4]);
        Wfr[i] = make_uint2(cvt_tf32(b0), cvt_tf32(b1));
    }
    // ---- stage params ----
    for (int j = tid; j < 192; j += THREADS) {
        gpsh[j] = make_float4(__ldg(&Wih[j * 3 + 0]), __ldg(&Wih[j * 3 + 1]),
                              __ldg(&Wih[j * 3 + 2]), __ldg(&bih[j]));
        bhsh[j] = __ldg(&bhh[j]);
    }
    if (tid < 64) wlsh[tid] = __ldg(&Wlin[tid]);
    // ---- stage hG = hid0 (padded rows), Lsh = last ----
    {
        const float4* hid04 = reinterpret_cast<const float4*>(hid0);
        for (int i = tid; i < BPC * 16; i += THREADS) {
            int b = i >> 4, c = i & 15;
            *reinterpret_cast<float4*>(hGsh + b * HPAD + c * 4) =
                __ldg(&hid04[(cb0 + b) * 16 + c]);
        }
    }
    if (tid < BPC) {
        int gb = cb0 + tid;
        Lsh[tid] = make_float4(__ldg(&last[gb * 3 + 0]),
                               __ldg(&last[gb * 3 + 1]),
                               __ldg(&last[gb * 3 + 2]), 0.0f);
    }

    // ---- Phase A identity: 8-lane group -> one batch, lane -> 8 dims
    const int sub = lane >> 3, lg = lane & 7;
    const int bA  = w * 4 + sub;
    const int gbA = cb0 + bA;
    const float4* Wl4 = reinterpret_cast<const float4*>(Wlin);
    const float4 wl0 = __ldg(&Wl4[lg * 2]);
    const float4 wl1 = __ldg(&Wl4[lg * 2 + 1]);
    const float  bl  = __ldg(blin);

    // encoder slice in registers: 12 t x 8 dims
    const float4* enc4 = reinterpret_cast<const float4*>(enc);
    float4 ev0[T_IN], ev1[T_IN];
#pragma unroll
    for (int t = 0; t < T_IN; t++) {
        int idx = (t * Bz + gbA) * 16 + lg * 2;
        ev0[t] = __ldg(&enc4[idx]);
        ev1[t] = __ldg(&enc4[idx + 1]);
    }

    // ---- Phase B identity: MMA fragment coords
    const int g  = lane >> 2;     // groupID 0..7
    const int t4 = lane & 3;      // threadID-in-group

    __syncthreads();

#pragma unroll 1
    for (int step = 0; step < T_OUT; step++) {
        // ================= Phase A: out(step-1) + attention =================
        float4 h0 = *reinterpret_cast<const float4*>(hGsh + bA * HPAD + lg * 8);
        float4 h1 = *reinterpret_cast<const float4*>(hGsh + bA * HPAD + lg * 8 + 4);

        if (step > 0) {
            float o = dot8(h0, wl0, h1, wl1);
            o += __shfl_xor_sync(FULLMASK, o, 4);
            o += __shfl_xor_sync(FULLMASK, o, 2);
            o += __shfl_xor_sync(FULLMASK, o, 1);
            o += bl;
            if (lg == 0) {
                float4 L = Lsh[bA];
                out[gbA * T_OUT + step - 1] = o;
                Lsh[bA] = make_float4(o, L.x, L.y, 0.0f);
            }
        }

        float p[T_IN];
#pragma unroll
        for (int t = 0; t < T_IN; t++)
            p[t] = dot8(ev0[t], h0, ev1[t], h1);
#pragma unroll
        for (int off = 4; off > 0; off >>= 1)
#pragma unroll
            for (int t = 0; t < T_IN; t++)
                p[t] += __shfl_xor_sync(FULLMASK, p[t], off);

        // tree-form max and sum (short critical path)
        float m;
        {
            float m0 = fmaxf(p[0], p[1]),  m1 = fmaxf(p[2], p[3]);
            float m2 = fmaxf(p[4], p[5]),  m3 = fmaxf(p[6], p[7]);
            float m4 = fmaxf(p[8], p[9]),  m5 = fmaxf(p[10], p[11]);
            float ma = fmaxf(m0, m1), mb = fmaxf(m2, m3), mc = fmaxf(m4, m5);
            m = fmaxf(fmaxf(ma, mb), mc);
        }
#pragma unroll
        for (int t = 0; t < T_IN; t++) p[t] = __expf(p[t] - m);
        float s;
        {
            float s0 = p[0] + p[1],  s1 = p[2] + p[3];
            float s2 = p[4] + p[5],  s3 = p[6] + p[7];
            float s4 = p[8] + p[9],  s5 = p[10] + p[11];
            float sa = s0 + s1, sb = s2 + s3, sc = s4 + s5;
            s = (sa + sb) + sc;
        }
        float inv = __fdividef(1.0f, s);

        float4 c0 = make_float4(0.f, 0.f, 0.f, 0.f);
        float4 c1 = make_float4(0.f, 0.f, 0.f, 0.f);
#pragma unroll
        for (int t = 0; t < T_IN; t++) {
            c0.x = fmaf(p[t], ev0[t].x, c0.x); c0.y = fmaf(p[t], ev0[t].y, c0.y);
            c0.z = fmaf(p[t], ev0[t].z, c0.z); c0.w = fmaf(p[t], ev0[t].w, c0.w);
            c1.x = fmaf(p[t], ev1[t].x, c1.x); c1.y = fmaf(p[t], ev1[t].y, c1.y);
            c1.z = fmaf(p[t], ev1[t].z, c1.z); c1.w = fmaf(p[t], ev1[t].w, c1.w);
        }
        h0.x = fmaf(c0.x, inv, h0.x); h0.y = fmaf(c0.y, inv, h0.y);
        h0.z = fmaf(c0.z, inv, h0.z); h0.w = fmaf(c0.w, inv, h0.w);
        h1.x = fmaf(c1.x, inv, h1.x); h1.y = fmaf(c1.y, inv, h1.y);
        h1.z = fmaf(c1.z, inv, h1.z); h1.w = fmaf(c1.w, inv, h1.w);

        *reinterpret_cast<float4*>(hAsh + bA * HPAD + lg * 8)     = h0;
        *reinterpret_cast<float4*>(hAsh + bA * HPAD + lg * 8 + 4) = h1;

        // ---- prefetch kt=0 B-fragments (step-invariant) BEFORE the barrier
        uint2 bv0[6];
#pragma unroll
        for (int nt = 0; nt < 6; nt++)
            bv0[nt] = Wfr[(((w * 6) + nt) * 8 + 0) * 32 + lane];

        __syncthreads();

        // ---- gate inputs needed later: issue loads early (in flight under MMA)
        float4 Lg0 = Lsh[g];
        float4 Lg8 = Lsh[g + 8];

        // ============ Phase B: gh = hA @ W_hh^T via tf32 MMA ============
        // warp w computes rows {gate*64 + w*16 + 0..15} for all 16 batches.
        float acc[6][4];
#pragma unroll
        for (int nt = 0; nt < 6; nt++)
#pragma unroll
            for (int ci = 0; ci < 4; ci++) acc[nt][ci] = 0.0f;

#pragma unroll
        for (int kt = 0; kt < 8; kt++) {
            // A fragment: a0:(g, k=kt8+t4) a1:(g+8, same) a2:(g, +4) a3:(g+8, +4)
            unsigned a0 = cvt_tf32(hAsh[g * HPAD + kt * 8 + t4]);
            unsigned a1 = cvt_tf32(hAsh[(g + 8) * HPAD + kt * 8 + t4]);
            unsigned a2 = cvt_tf32(hAsh[g * HPAD + kt * 8 + t4 + 4]);
            unsigned a3 = cvt_tf32(hAsh[(g + 8) * HPAD + kt * 8 + t4 + 4]);
#pragma unroll
            for (int nt = 0; nt < 6; nt++) {
                uint2 bv = (kt == 0) ? bv0[nt]
                                     : Wfr[(((w * 6) + nt) * 8 + kt) * 32 + lane];
                mma_tf32(acc[nt][0], acc[nt][1], acc[nt][2], acc[nt][3],
                         a0, a1, a2, a3, bv.x, bv.y);
            }
        }

        // ---- gates: lane covers batches {g, g+8} x dims {w16+ntp8+2t4, +1}
#pragma unroll
        for (int ntp = 0; ntp < 2; ntp++) {
#pragma unroll
            for (int d01 = 0; d01 < 2; d01++) {
                int dim = w * 16 + ntp * 8 + 2 * t4 + d01;
                float4 gpr = gpsh[dim];
                float4 gpz = gpsh[64 + dim];
                float4 gpn = gpsh[128 + dim];
                float bhr = bhsh[dim], bhz = bhsh[64 + dim], bhn = bhsh[128 + dim];
#pragma unroll
                for (int bb = 0; bb < 2; bb++) {
                    int bat = g + 8 * bb;
                    float4 L = bb ? Lg8 : Lg0;
                    int ci = bb * 2 + d01;
                    float ghr = acc[ntp][ci]     + bhr;
                    float ghz = acc[ntp + 2][ci] + bhz;
                    float ghn = acc[ntp + 4][ci] + bhn;
                    float gir = fmaf(gpr.x, L.x, fmaf(gpr.y, L.y, fmaf(gpr.z, L.z, gpr.w)));
                    float giz = fmaf(gpz.x, L.x, fmaf(gpz.y, L.y, fmaf(gpz.z, L.z, gpz.w)));
                    float gin = fmaf(gpn.x, L.x, fmaf(gpn.y, L.y, fmaf(gpn.z, L.z, gpn.w)));
                    float r = sigf(gir + ghr);
                    float z = sigf(giz + ghz);
                    float n = tanhfast(fmaf(r, ghn, gin));
                    float hprev = hAsh[bat * HPAD + dim];
                    hGsh[bat * HPAD + dim] = fmaf(z, hprev - n, n);
                }
            }
        }
        __syncthreads();
    }

    // ---- final output (step T_OUT-1) from hG ----
    {
        float4 h0 = *reinterpret_cast<const float4*>(hGsh + bA * HPAD + lg * 8);
        float4 h1 = *reinterpret_cast<const float4*>(hGsh + bA * HPAD + lg * 8 + 4);
        float o = dot8(h0, wl0, h1, wl1);
        o += __shfl_xor_sync(FULLMASK, o, 4);
        o += __shfl_xor_sync(FULLMASK, o, 2);
        o += __shfl_xor_sync(FULLMASK, o, 1);
        o += bl;
        if (lg == 0) out[gbA * T_OUT + T_OUT - 1] = o;
    }
}

extern "C" void kernel_launch(void* const* d_in, const int* in_sizes, int n_in,
                              void* d_out, int out_size) {
    const float* enc  = (const float*)d_in[0];
    const float* hid0 = (const float*)d_in[1];
    const float* last = (const float*)d_in[2];
    const float* Wih  = (const float*)d_in[3];
    const float* Whh  = (const float*)d_in[4];
    const float* bih  = (const float*)d_in[5];
    const float* bhh  = (const float*)d_in[6];
    const float* Wlin = (const float*)d_in[7];
    const float* blin = (const float*)d_in[8];
    float* out = (float*)d_out;

    cudaFuncSetAttribute(decoder_kernel,
                         cudaFuncAttributeMaxDynamicSharedMemorySize,
                         SMEM_BYTES);

    dim3 grid(Bz / BPC);   // 4096 CTAs
    decoder_kernel<<<grid, THREADS, SMEM_BYTES>>>(
        enc, hid0, last, Wih, Whh, bih, bhh, Wlin, blin, out);
}